// round 1
// baseline (speedup 1.0000x reference)
#include <cuda_runtime.h>
#include <cuda_bf16.h>
#include <math.h>

// Problem dims (fixed by the reference)
#define TDIM 4096
#define CDIM 2048
#define NF   2048
#define N3   6144   // 3*NF

// Scratch: qkv (T x 3NF) and P (T x T), both fp32.
__device__ float g_qkv[(size_t)TDIM * N3];   // 96 MB
__device__ float g_P[(size_t)TDIM * TDIM];   // 64 MB

// ---------------------------------------------------------------------------
// Kernel 1: qkv = x @ W + b   (M=TDIM, N=N3, K=CDIM), classic 128x128x8 SGEMM
// ---------------------------------------------------------------------------
__global__ __launch_bounds__(256)
void k_gemm_qkv(const float* __restrict__ A,   // x: TDIM x CDIM
                const float* __restrict__ B,   // W: CDIM x N3
                const float* __restrict__ bias)
{
    __shared__ float As[8][128];
    __shared__ float Bs[8][128];

    const int bx = blockIdx.x;   // N tile
    const int by = blockIdx.y;   // M tile
    const int tid = threadIdx.x;

    const int rowA = tid >> 1;          // 0..127
    const int colA = (tid & 1) << 2;    // 0 or 4
    const int rowB = tid >> 5;          // 0..7
    const int colB = (tid & 31) << 2;   // 0..124

    const float* Aptr = A + (size_t)(by * 128 + rowA) * CDIM + colA;
    const float* Bptr = B + (size_t)rowB * N3 + bx * 128 + colB;

    const int tr = (tid >> 4) << 3;   // thread row base in tile
    const int tc = (tid & 15) << 3;   // thread col base in tile

    float acc[8][8];
    #pragma unroll
    for (int i = 0; i < 8; i++)
        #pragma unroll
        for (int j = 0; j < 8; j++) acc[i][j] = 0.f;

    for (int k0 = 0; k0 < CDIM; k0 += 8) {
        float4 a4 = *(const float4*)(Aptr + k0);
        float4 b4 = *(const float4*)(Bptr + (size_t)k0 * N3);
        As[colA + 0][rowA] = a4.x;
        As[colA + 1][rowA] = a4.y;
        As[colA + 2][rowA] = a4.z;
        As[colA + 3][rowA] = a4.w;
        *(float4*)&Bs[rowB][colB] = b4;
        __syncthreads();

        #pragma unroll
        for (int kk = 0; kk < 8; kk++) {
            float4 a0 = *(const float4*)&As[kk][tr];
            float4 a1 = *(const float4*)&As[kk][tr + 4];
            float4 b0 = *(const float4*)&Bs[kk][tc];
            float4 b1 = *(const float4*)&Bs[kk][tc + 4];
            float ar[8] = {a0.x,a0.y,a0.z,a0.w,a1.x,a1.y,a1.z,a1.w};
            float br[8] = {b0.x,b0.y,b0.z,b0.w,b1.x,b1.y,b1.z,b1.w};
            #pragma unroll
            for (int i = 0; i < 8; i++)
                #pragma unroll
                for (int j = 0; j < 8; j++)
                    acc[i][j] = fmaf(ar[i], br[j], acc[i][j]);
        }
        __syncthreads();
    }

    #pragma unroll
    for (int i = 0; i < 8; i++) {
        const int row = by * 128 + tr + i;
        float* crow = g_qkv + (size_t)row * N3 + bx * 128 + tc;
        const float* bp = bias + bx * 128 + tc;
        #pragma unroll
        for (int j = 0; j < 8; j += 4) {
            float4 o;
            o.x = acc[i][j+0] + bp[j+0];
            o.y = acc[i][j+1] + bp[j+1];
            o.z = acc[i][j+2] + bp[j+2];
            o.w = acc[i][j+3] + bp[j+3];
            *(float4*)(crow + j) = o;
        }
    }
}

// ---------------------------------------------------------------------------
// Kernel 2: S = scale * Q @ K^T  (NT), skipping masked blocks entirely.
// Q = g_qkv[:, 0:NF], K = g_qkv[:, NF:2NF], pitch N3. S pitch TDIM.
// ---------------------------------------------------------------------------
__global__ __launch_bounds__(256)
void k_gemm_s(const int* __restrict__ n_padd_p)
{
    const int np = *n_padd_p;
    const int rm = blockIdx.y * 128;
    const int cn = blockIdx.x * 128;
    // skip blocks fully above the diagonal or fully inside padding bands
    if (cn >= rm + 128) return;
    if (cn + 128 <= np) return;
    if (rm + 128 <= np) return;

    __shared__ float As[8][128];
    __shared__ float Bs[8][128];

    const int tid = threadIdx.x;
    const int rowA = tid >> 1;
    const int colA = (tid & 1) << 2;

    const float* Qptr = g_qkv + (size_t)(rm + rowA) * N3 + colA;            // Q
    const float* Kptr = g_qkv + (size_t)(cn + rowA) * N3 + NF + colA;       // K

    const int tr = (tid >> 4) << 3;
    const int tc = (tid & 15) << 3;

    float acc[8][8];
    #pragma unroll
    for (int i = 0; i < 8; i++)
        #pragma unroll
        for (int j = 0; j < 8; j++) acc[i][j] = 0.f;

    for (int k0 = 0; k0 < NF; k0 += 8) {
        float4 a4 = *(const float4*)(Qptr + k0);
        float4 b4 = *(const float4*)(Kptr + k0);
        As[colA + 0][rowA] = a4.x;
        As[colA + 1][rowA] = a4.y;
        As[colA + 2][rowA] = a4.z;
        As[colA + 3][rowA] = a4.w;
        Bs[colA + 0][rowA] = b4.x;
        Bs[colA + 1][rowA] = b4.y;
        Bs[colA + 2][rowA] = b4.z;
        Bs[colA + 3][rowA] = b4.w;
        __syncthreads();

        #pragma unroll
        for (int kk = 0; kk < 8; kk++) {
            float4 a0 = *(const float4*)&As[kk][tr];
            float4 a1 = *(const float4*)&As[kk][tr + 4];
            float4 b0 = *(const float4*)&Bs[kk][tc];
            float4 b1 = *(const float4*)&Bs[kk][tc + 4];
            float ar[8] = {a0.x,a0.y,a0.z,a0.w,a1.x,a1.y,a1.z,a1.w};
            float br[8] = {b0.x,b0.y,b0.z,b0.w,b1.x,b1.y,b1.z,b1.w};
            #pragma unroll
            for (int i = 0; i < 8; i++)
                #pragma unroll
                for (int j = 0; j < 8; j++)
                    acc[i][j] = fmaf(ar[i], br[j], acc[i][j]);
        }
        __syncthreads();
    }

    const float scale = rsqrtf((float)NF);
    #pragma unroll
    for (int i = 0; i < 8; i++) {
        const int row = rm + tr + i;
        float* srow = g_P + 0; // placeholder to keep compiler honest
        (void)srow;
        float* out = ((float*)g_P, (float*)0); (void)out;
        float* sdst = (float*)g_qkv; (void)sdst;
        #pragma unroll
        for (int j = 0; j < 8; j += 4) {
            float4 o;
            o.x = acc[i][j+0] * scale;
            o.y = acc[i][j+1] * scale;
            o.z = acc[i][j+2] * scale;
            o.w = acc[i][j+3] * scale;
            *(float4*)(&g_P[(size_t)row * TDIM + cn + tc + j]) = o;
        }
    }
}

// ---------------------------------------------------------------------------
// Kernel 3: row softmax in-place on g_P (S was written into g_P).
// Row r: valid cols [np, r]; everything else set to 0. Rows < np fully zero.
// ---------------------------------------------------------------------------
__global__ __launch_bounds__(256)
void k_softmax(const int* __restrict__ n_padd_p)
{
    const int r = blockIdx.x;
    const int np = *n_padd_p;
    const int tid = threadIdx.x;
    __shared__ float red[256];

    float* prow = g_P + (size_t)r * TDIM;

    if (r < np) {
        float4 z = make_float4(0.f, 0.f, 0.f, 0.f);
        for (int i = tid; i < TDIM / 4; i += 256)
            ((float4*)prow)[i] = z;
        return;
    }

    // 1) max over valid range
    float m = -3.402823466e+38f;
    for (int c = np + tid; c <= r; c += 256) m = fmaxf(m, prow[c]);
    red[tid] = m; __syncthreads();
    for (int s = 128; s > 0; s >>= 1) {
        if (tid < s) red[tid] = fmaxf(red[tid], red[tid + s]);
        __syncthreads();
    }
    m = red[0];
    __syncthreads();

    // 2) zero the masked regions, exponentiate valid region, accumulate sum
    for (int c = tid; c < np; c += 256) prow[c] = 0.f;
    for (int c = r + 1 + tid; c < TDIM; c += 256) prow[c] = 0.f;
    float sum = 0.f;
    for (int c = np + tid; c <= r; c += 256) {
        float e = __expf(prow[c] - m);
        prow[c] = e;
        sum += e;
    }
    red[tid] = sum; __syncthreads();
    for (int s = 128; s > 0; s >>= 1) {
        if (tid < s) red[tid] += red[tid + s];
        __syncthreads();
    }
    const float inv = 1.0f / red[0];

    // 3) normalize
    for (int c = np + tid; c <= r; c += 256) prow[c] *= inv;
}

// ---------------------------------------------------------------------------
// Kernel 4: y = P @ V   (M=TDIM, N=NF, K=TDIM), K-range clipped per block row.
// V = g_qkv[:, 2NF:3NF], pitch N3.
// ---------------------------------------------------------------------------
__global__ __launch_bounds__(256)
void k_gemm_pv(const int* __restrict__ n_padd_p, float* __restrict__ C)
{
    const int np = *n_padd_p;
    const int rm = blockIdx.y * 128;
    const int cn = blockIdx.x * 128;

    const int kstart = np & ~7;         // floor to BK multiple; P is 0 below np
    const int kend   = rm + 128;        // P[r][c]=0 for c>r, so this covers it

    __shared__ float As[8][128];
    __shared__ float Bs[8][128];

    const int tid = threadIdx.x;
    const int rowA = tid >> 1;
    const int colA = (tid & 1) << 2;
    const int rowB = tid >> 5;
    const int colB = (tid & 31) << 2;

    const float* Aptr = g_P + (size_t)(rm + rowA) * TDIM + colA;
    const float* Bbase = g_qkv + 2 * NF + cn + colB;   // V tile columns

    const int tr = (tid >> 4) << 3;
    const int tc = (tid & 15) << 3;

    float acc[8][8];
    #pragma unroll
    for (int i = 0; i < 8; i++)
        #pragma unroll
        for (int j = 0; j < 8; j++) acc[i][j] = 0.f;

    for (int k0 = kstart; k0 < kend; k0 += 8) {
        float4 a4 = *(const float4*)(Aptr + k0);
        float4 b4 = *(const float4*)(Bbase + (size_t)(k0 + rowB) * N3);
        As[colA + 0][rowA] = a4.x;
        As[colA + 1][rowA] = a4.y;
        As[colA + 2][rowA] = a4.z;
        As[colA + 3][rowA] = a4.w;
        *(float4*)&Bs[rowB][colB] = b4;
        __syncthreads();

        #pragma unroll
        for (int kk = 0; kk < 8; kk++) {
            float4 a0 = *(const float4*)&As[kk][tr];
            float4 a1 = *(const float4*)&As[kk][tr + 4];
            float4 b0 = *(const float4*)&Bs[kk][tc];
            float4 b1 = *(const float4*)&Bs[kk][tc + 4];
            float ar[8] = {a0.x,a0.y,a0.z,a0.w,a1.x,a1.y,a1.z,a1.w};
            float br[8] = {b0.x,b0.y,b0.z,b0.w,b1.x,b1.y,b1.z,b1.w};
            #pragma unroll
            for (int i = 0; i < 8; i++)
                #pragma unroll
                for (int j = 0; j < 8; j++)
                    acc[i][j] = fmaf(ar[i], br[j], acc[i][j]);
        }
        __syncthreads();
    }

    #pragma unroll
    for (int i = 0; i < 8; i++) {
        const int row = rm + tr + i;
        float* crow = C + (size_t)row * NF + cn + tc;
        #pragma unroll
        for (int j = 0; j < 8; j += 4) {
            float4 o;
            o.x = acc[i][j+0];
            o.y = acc[i][j+1];
            o.z = acc[i][j+2];
            o.w = acc[i][j+3];
            *(float4*)(crow + j) = o;
        }
    }
}

// ---------------------------------------------------------------------------
extern "C" void kernel_launch(void* const* d_in, const int* in_sizes, int n_in,
                              void* d_out, int out_size)
{
    const float* x  = (const float*)d_in[0];   // (4096, 2048)
    const float* W  = (const float*)d_in[1];   // (2048, 6144)
    const float* b  = (const float*)d_in[2];   // (6144,)
    const int*   np = (const int*)d_in[3];     // scalar
    float* y = (float*)d_out;                  // (4096, 2048)
    (void)in_sizes; (void)n_in; (void)out_size;

    dim3 t(256);
    dim3 g_qkv_grid(N3 / 128, TDIM / 128);     // 48 x 32
    dim3 g_s_grid(TDIM / 128, TDIM / 128);     // 32 x 32
    dim3 g_pv_grid(NF / 128, TDIM / 128);      // 16 x 32

    k_gemm_qkv<<<g_qkv_grid, t>>>(x, W, b);
    k_gemm_s<<<g_s_grid, t>>>(np);
    k_softmax<<<TDIM, t>>>(np);
    k_gemm_pv<<<g_pv_grid, t>>>(np, y);
}

// round 2
// speedup vs baseline: 3.2866x; 3.2866x over previous
#include <cuda_runtime.h>
#include <cuda_bf16.h>
#include <cstdint>
#include <math.h>

// Problem dims (fixed by the reference)
#define TDIM 4096
#define CDIM 2048
#define NF   2048
#define N3   6144   // 3*NF

#define BM 128
#define BN 128
#define BK 32
#define SA 36    // A-style tile stride ([row][k]), conflict-free
#define SB 136   // B NN tile stride ([k][n]), conflict-free

// Scratch: qkv (T x 3NF) and P (T x T), both fp32.
__device__ float g_qkv[(size_t)TDIM * N3];   // 96 MB
__device__ float g_P[(size_t)TDIM * TDIM];   // 64 MB

__device__ __forceinline__ uint32_t f2tf32(float x) {
    uint32_t u;
    asm("cvt.rna.tf32.f32 %0, %1;" : "=r"(u) : "f"(x));
    return u;
}

__device__ __forceinline__ void mma_tf32(float* d,
    uint32_t a0, uint32_t a1, uint32_t a2, uint32_t a3,
    uint32_t b0, uint32_t b1)
{
    asm volatile(
        "mma.sync.aligned.m16n8k8.row.col.f32.tf32.tf32.f32 "
        "{%0,%1,%2,%3}, {%4,%5,%6,%7}, {%8,%9}, {%0,%1,%2,%3};\n"
        : "+f"(d[0]), "+f"(d[1]), "+f"(d[2]), "+f"(d[3])
        : "r"(a0), "r"(a1), "r"(a2), "r"(a3), "r"(b0), "r"(b1));
}

// Load a 128x32 row-major fp32 tile (row pitch `ld`) into tile[row][k] (stride SA),
// converting to tf32. 256 threads.
__device__ __forceinline__ void load_tileA(uint32_t (*tile)[SA],
                                           const float* __restrict__ src,
                                           size_t ld, int tid)
{
    #pragma unroll
    for (int i = 0; i < 4; i++) {
        int idx = tid + i * 256;
        int r = idx >> 3;             // 0..127
        int k = (idx & 7) << 2;       // 0..28
        float4 v = *(const float4*)(src + (size_t)r * ld + k);
        uint4 u;
        u.x = f2tf32(v.x); u.y = f2tf32(v.y);
        u.z = f2tf32(v.z); u.w = f2tf32(v.w);
        *(uint4*)&tile[r][k] = u;
    }
}

// Load a 32x128 row-major fp32 tile (row pitch `ld`) into tile[k][n] (stride SB).
__device__ __forceinline__ void load_tileB(uint32_t (*tile)[SB],
                                           const float* __restrict__ src,
                                           size_t ld, int tid)
{
    #pragma unroll
    for (int i = 0; i < 4; i++) {
        int idx = tid + i * 256;
        int k = idx >> 5;             // 0..31
        int n = (idx & 31) << 2;      // 0..124
        float4 v = *(const float4*)(src + (size_t)k * ld + n);
        uint4 u;
        u.x = f2tf32(v.x); u.y = f2tf32(v.y);
        u.z = f2tf32(v.z); u.w = f2tf32(v.w);
        *(uint4*)&tile[k][n] = u;
    }
}

// ---------------------------------------------------------------------------
// Kernel 1: qkv = x @ W + b   (M=TDIM, N=N3, K=CDIM), tf32 MMA, NN
// ---------------------------------------------------------------------------
__global__ __launch_bounds__(256, 2)
void k_gemm_qkv(const float* __restrict__ A,   // x: TDIM x CDIM
                const float* __restrict__ B,   // W: CDIM x N3
                const float* __restrict__ bias)
{
    __shared__ uint32_t As[BM][SA];
    __shared__ uint32_t Bs[BK][SB];

    const int tid = threadIdx.x;
    const int lane = tid & 31;
    const int wid  = tid >> 5;
    const int wm = wid & 1;      // 0..1 -> 64 rows
    const int wn = wid >> 1;     // 0..3 -> 32 cols
    const int g  = lane >> 2;
    const int t4 = lane & 3;

    const int m0 = blockIdx.y * BM;
    const int n0 = blockIdx.x * BN;

    float acc[16][4];
    #pragma unroll
    for (int i = 0; i < 16; i++)
        #pragma unroll
        for (int j = 0; j < 4; j++) acc[i][j] = 0.f;

    for (int k0 = 0; k0 < CDIM; k0 += BK) {
        load_tileA(As, A + (size_t)m0 * CDIM + k0, CDIM, tid);
        load_tileB(Bs, B + (size_t)k0 * N3 + n0, N3, tid);
        __syncthreads();

        #pragma unroll
        for (int ks = 0; ks < 4; ks++) {
            const int kb = ks * 8;
            uint32_t af[4][4], bf[4][2];
            #pragma unroll
            for (int mt = 0; mt < 4; mt++) {
                const int m = wm * 64 + mt * 16 + g;
                af[mt][0] = As[m    ][kb + t4];
                af[mt][1] = As[m + 8][kb + t4];
                af[mt][2] = As[m    ][kb + t4 + 4];
                af[mt][3] = As[m + 8][kb + t4 + 4];
            }
            #pragma unroll
            for (int nt = 0; nt < 4; nt++) {
                const int n = wn * 32 + nt * 8 + g;
                bf[nt][0] = Bs[kb + t4    ][n];
                bf[nt][1] = Bs[kb + t4 + 4][n];
            }
            #pragma unroll
            for (int mt = 0; mt < 4; mt++)
                #pragma unroll
                for (int nt = 0; nt < 4; nt++)
                    mma_tf32(acc[mt * 4 + nt],
                             af[mt][0], af[mt][1], af[mt][2], af[mt][3],
                             bf[nt][0], bf[nt][1]);
        }
        __syncthreads();
    }

    #pragma unroll
    for (int mt = 0; mt < 4; mt++) {
        #pragma unroll
        for (int nt = 0; nt < 4; nt++) {
            const int row = m0 + wm * 64 + mt * 16 + g;
            const int col = n0 + wn * 32 + nt * 8 + t4 * 2;
            const float b0 = bias[col], b1 = bias[col + 1];
            float* p0 = g_qkv + (size_t)row * N3 + col;
            float* p1 = g_qkv + (size_t)(row + 8) * N3 + col;
            float2 v0 = make_float2(acc[mt*4+nt][0] + b0, acc[mt*4+nt][1] + b1);
            float2 v1 = make_float2(acc[mt*4+nt][2] + b0, acc[mt*4+nt][3] + b1);
            *(float2*)p0 = v0;
            *(float2*)p1 = v1;
        }
    }
}

// ---------------------------------------------------------------------------
// Kernel 2: S = scale * Q @ K^T  (NT), tf32 MMA, skipping masked blocks.
// ---------------------------------------------------------------------------
__global__ __launch_bounds__(256, 2)
void k_gemm_s(const int* __restrict__ n_padd_p)
{
    const int np = *n_padd_p;
    const int rm = blockIdx.y * BM;
    const int cn = blockIdx.x * BN;
    if (cn >= rm + BM) return;          // fully above diagonal
    if (cn + BN <= np) return;          // cols fully in padding
    if (rm + BM <= np) return;          // rows fully in padding

    __shared__ uint32_t As[BM][SA];
    __shared__ uint32_t Ks[BN][SA];

    const int tid = threadIdx.x;
    const int lane = tid & 31;
    const int wid  = tid >> 5;
    const int wm = wid & 1;
    const int wn = wid >> 1;
    const int g  = lane >> 2;
    const int t4 = lane & 3;

    float acc[16][4];
    #pragma unroll
    for (int i = 0; i < 16; i++)
        #pragma unroll
        for (int j = 0; j < 4; j++) acc[i][j] = 0.f;

    for (int k0 = 0; k0 < NF; k0 += BK) {
        load_tileA(As, g_qkv + (size_t)rm * N3 + k0,       N3, tid);   // Q rows
        load_tileA(Ks, g_qkv + (size_t)cn * N3 + NF + k0,  N3, tid);   // K rows
        __syncthreads();

        #pragma unroll
        for (int ks = 0; ks < 4; ks++) {
            const int kb = ks * 8;
            uint32_t af[4][4], bf[4][2];
            #pragma unroll
            for (int mt = 0; mt < 4; mt++) {
                const int m = wm * 64 + mt * 16 + g;
                af[mt][0] = As[m    ][kb + t4];
                af[mt][1] = As[m + 8][kb + t4];
                af[mt][2] = As[m    ][kb + t4 + 4];
                af[mt][3] = As[m + 8][kb + t4 + 4];
            }
            #pragma unroll
            for (int nt = 0; nt < 4; nt++) {
                const int n = wn * 32 + nt * 8 + g;
                bf[nt][0] = Ks[n][kb + t4];
                bf[nt][1] = Ks[n][kb + t4 + 4];
            }
            #pragma unroll
            for (int mt = 0; mt < 4; mt++)
                #pragma unroll
                for (int nt = 0; nt < 4; nt++)
                    mma_tf32(acc[mt * 4 + nt],
                             af[mt][0], af[mt][1], af[mt][2], af[mt][3],
                             bf[nt][0], bf[nt][1]);
        }
        __syncthreads();
    }

    const float scale = rsqrtf((float)NF);
    #pragma unroll
    for (int mt = 0; mt < 4; mt++) {
        #pragma unroll
        for (int nt = 0; nt < 4; nt++) {
            const int row = rm + wm * 64 + mt * 16 + g;
            const int col = cn + wn * 32 + nt * 8 + t4 * 2;
            float* p0 = g_P + (size_t)row * TDIM + col;
            float* p1 = g_P + (size_t)(row + 8) * TDIM + col;
            *(float2*)p0 = make_float2(acc[mt*4+nt][0] * scale, acc[mt*4+nt][1] * scale);
            *(float2*)p1 = make_float2(acc[mt*4+nt][2] * scale, acc[mt*4+nt][3] * scale);
        }
    }
}

// ---------------------------------------------------------------------------
// Kernel 3: row softmax in-place on g_P.
// ---------------------------------------------------------------------------
__global__ __launch_bounds__(256)
void k_softmax(const int* __restrict__ n_padd_p)
{
    const int r = blockIdx.x;
    const int np = *n_padd_p;
    const int tid = threadIdx.x;
    __shared__ float red[256];

    float* prow = g_P + (size_t)r * TDIM;

    if (r < np) {
        float4 z = make_float4(0.f, 0.f, 0.f, 0.f);
        for (int i = tid; i < TDIM / 4; i += 256)
            ((float4*)prow)[i] = z;
        return;
    }

    float m = -3.402823466e+38f;
    for (int c = np + tid; c <= r; c += 256) m = fmaxf(m, prow[c]);
    red[tid] = m; __syncthreads();
    for (int s = 128; s > 0; s >>= 1) {
        if (tid < s) red[tid] = fmaxf(red[tid], red[tid + s]);
        __syncthreads();
    }
    m = red[0];
    __syncthreads();

    for (int c = tid; c < np; c += 256) prow[c] = 0.f;
    for (int c = r + 1 + tid; c < TDIM; c += 256) prow[c] = 0.f;
    float sum = 0.f;
    for (int c = np + tid; c <= r; c += 256) {
        float e = __expf(prow[c] - m);
        prow[c] = e;
        sum += e;
    }
    red[tid] = sum; __syncthreads();
    for (int s = 128; s > 0; s >>= 1) {
        if (tid < s) red[tid] += red[tid + s];
        __syncthreads();
    }
    const float inv = 1.0f / red[0];

    for (int c = np + tid; c <= r; c += 256) prow[c] *= inv;
}

// ---------------------------------------------------------------------------
// Kernel 4: y = P @ V  (NN), tf32 MMA, K-range clipped per block row.
// ---------------------------------------------------------------------------
__global__ __launch_bounds__(256, 2)
void k_gemm_pv(const int* __restrict__ n_padd_p, float* __restrict__ C)
{
    const int np = *n_padd_p;
    const int rm = blockIdx.y * BM;
    const int cn = blockIdx.x * BN;

    const int kstart = np & ~(BK - 1);
    const int kend   = rm + BM;

    __shared__ uint32_t As[BM][SA];
    __shared__ uint32_t Bs[BK][SB];

    const int tid = threadIdx.x;
    const int lane = tid & 31;
    const int wid  = tid >> 5;
    const int wm = wid & 1;
    const int wn = wid >> 1;
    const int g  = lane >> 2;
    const int t4 = lane & 3;

    float acc[16][4];
    #pragma unroll
    for (int i = 0; i < 16; i++)
        #pragma unroll
        for (int j = 0; j < 4; j++) acc[i][j] = 0.f;

    for (int k0 = kstart; k0 < kend; k0 += BK) {
        load_tileA(As, g_P + (size_t)rm * TDIM + k0, TDIM, tid);
        load_tileB(Bs, g_qkv + (size_t)k0 * N3 + 2 * NF + cn, N3, tid);
        __syncthreads();

        #pragma unroll
        for (int ks = 0; ks < 4; ks++) {
            const int kb = ks * 8;
            uint32_t af[4][4], bf[4][2];
            #pragma unroll
            for (int mt = 0; mt < 4; mt++) {
                const int m = wm * 64 + mt * 16 + g;
                af[mt][0] = As[m    ][kb + t4];
                af[mt][1] = As[m + 8][kb + t4];
                af[mt][2] = As[m    ][kb + t4 + 4];
                af[mt][3] = As[m + 8][kb + t4 + 4];
            }
            #pragma unroll
            for (int nt = 0; nt < 4; nt++) {
                const int n = wn * 32 + nt * 8 + g;
                bf[nt][0] = Bs[kb + t4    ][n];
                bf[nt][1] = Bs[kb + t4 + 4][n];
            }
            #pragma unroll
            for (int mt = 0; mt < 4; mt++)
                #pragma unroll
                for (int nt = 0; nt < 4; nt++)
                    mma_tf32(acc[mt * 4 + nt],
                             af[mt][0], af[mt][1], af[mt][2], af[mt][3],
                             bf[nt][0], bf[nt][1]);
        }
        __syncthreads();
    }

    #pragma unroll
    for (int mt = 0; mt < 4; mt++) {
        #pragma unroll
        for (int nt = 0; nt < 4; nt++) {
            const int row = rm + wm * 64 + mt * 16 + g;
            const int col = cn + wn * 32 + nt * 8 + t4 * 2;
            float* p0 = C + (size_t)row * NF + col;
            float* p1 = C + (size_t)(row + 8) * NF + col;
            *(float2*)p0 = make_float2(acc[mt*4+nt][0], acc[mt*4+nt][1]);
            *(float2*)p1 = make_float2(acc[mt*4+nt][2], acc[mt*4+nt][3]);
        }
    }
}

// ---------------------------------------------------------------------------
extern "C" void kernel_launch(void* const* d_in, const int* in_sizes, int n_in,
                              void* d_out, int out_size)
{
    const float* x  = (const float*)d_in[0];   // (4096, 2048)
    const float* W  = (const float*)d_in[1];   // (2048, 6144)
    const float* b  = (const float*)d_in[2];   // (6144,)
    const int*   np = (const int*)d_in[3];     // scalar
    float* y = (float*)d_out;                  // (4096, 2048)
    (void)in_sizes; (void)n_in; (void)out_size;

    dim3 t(256);
    dim3 grid_qkv(N3 / BN, TDIM / BM);   // 48 x 32
    dim3 grid_s(TDIM / BN, TDIM / BM);   // 32 x 32
    dim3 grid_pv(NF / BN, TDIM / BM);    // 16 x 32

    k_gemm_qkv<<<grid_qkv, t>>>(x, W, b);
    k_gemm_s<<<grid_s, t>>>(np);
    k_softmax<<<TDIM, t>>>(np);
    k_gemm_pv<<<grid_pv, t>>>(np, y);
}